// round 15
// baseline (speedup 1.0000x reference)
#include <cuda_runtime.h>
#include <cuda_fp16.h>
#include <cstdint>

#define BSZ  512
#define SRCN 36
#define HD   1024
#define MD   4096
#define NTOK (BSZ*SRCN)       // 18432
#define ALPHA_F 8.0f
#define INV_ALPHA_F 0.125f
#define GAMMA_F 0.98f

// ---------------- scratch (device globals: allocation-guard safe) ----------
__device__ float g_ru_sum;
__device__ float g_w[NTOK];
__device__ __align__(16) __half g_mmh[(size_t)NTOK * HD];
__device__ __align__(16) __half g_h  [(size_t)NTOK * MD];
__device__ __align__(16) __half g_fch[(size_t)NTOK * HD];
__device__ __align__(16) __half g_W1h[(size_t)HD * MD];
__device__ __align__(16) __half g_W2h[(size_t)MD * HD];

// ---------------- PTX helpers ------------------------------------------------
__device__ __forceinline__ uint32_t smem_u32(const void* p) {
    uint32_t a;
    asm("{ .reg .u64 t; cvta.to.shared.u64 t, %1; cvt.u32.u64 %0, t; }" : "=r"(a) : "l"(p));
    return a;
}
__device__ __forceinline__ void cp16(uint32_t dst, const void* src) {
    asm volatile("cp.async.cg.shared.global [%0], [%1], 16;" :: "r"(dst), "l"(src));
}
__device__ __forceinline__ void cp_commit() {
    asm volatile("cp.async.commit_group;" ::: "memory");
}
template <int N>
__device__ __forceinline__ void cp_wait() {
    asm volatile("cp.async.wait_group %0;" :: "n"(N) : "memory");
}
__device__ __forceinline__ void ldsm_x4(uint32_t* r, uint32_t addr) {
    asm volatile("ldmatrix.sync.aligned.m8n8.x4.shared.b16 {%0,%1,%2,%3}, [%4];"
                 : "=r"(r[0]), "=r"(r[1]), "=r"(r[2]), "=r"(r[3]) : "r"(addr));
}
__device__ __forceinline__ void ldsm_x4_t(uint32_t* r, uint32_t addr) {
    asm volatile("ldmatrix.sync.aligned.m8n8.x4.trans.shared.b16 {%0,%1,%2,%3}, [%4];"
                 : "=r"(r[0]), "=r"(r[1]), "=r"(r[2]), "=r"(r[3]) : "r"(addr));
}
__device__ __forceinline__ void mma_f16(float* c, const uint32_t* a, const uint32_t* b) {
    asm volatile(
        "mma.sync.aligned.m16n8k16.row.col.f32.f16.f16.f32 "
        "{%0,%1,%2,%3},{%4,%5,%6,%7},{%8,%9},{%0,%1,%2,%3};"
        : "+f"(c[0]), "+f"(c[1]), "+f"(c[2]), "+f"(c[3])
        : "r"(a[0]), "r"(a[1]), "r"(a[2]), "r"(a[3]), "r"(b[0]), "r"(b[1]));
}
__device__ __forceinline__ void sts32(uint32_t addr, uint32_t v) {
    asm volatile("st.shared.b32 [%0], %1;" :: "r"(addr), "r"(v) : "memory");
}
__device__ __forceinline__ void lds128(uint32_t addr, uint32_t* r) {
    asm volatile("ld.shared.v4.b32 {%0,%1,%2,%3}, [%4];"
                 : "=r"(r[0]), "=r"(r[1]), "=r"(r[2]), "=r"(r[3]) : "r"(addr));
}

// ============================ fp16 HMMA GEMM =================================
// R12 champion mainloop: 128x128 block, 2x4 warps of 64x32, TKH=32, 6 stages,
// 2 k-tiles per barrier, race-free re-indexed prefetch, pair loop unrolled 3x.
// R15: epilogue stages C tile through smem (272B padded rows, conflict-free)
// and flushes with LDS.128 + fully-coalesced STG.128.
#define TM 128
#define TN 128
#define TKH 32
#define NSTAGE 6
#define A_STG 8192
#define B_STG 8192
#define STG (A_STG + B_STG)
#define SMEM_DYN (NSTAGE * STG)
#define C_ROWB 272               // 128 cols * 2B + 16B pad

__device__ __forceinline__ uint32_t a_off(int row, int c16) {
    const int sr = row >> 1;
    const int ch = (row & 1) * 4 + c16;
    return (uint32_t)(sr * 128 + ((ch ^ (sr & 7)) << 4));
}
__device__ __forceinline__ uint32_t b_off(int k, int c16) {
    return (uint32_t)(A_STG + k * 256 + (((c16 & 8) | ((c16 ^ k) & 7)) << 4));
}

template <int RELU>
__global__ __launch_bounds__(256, 2) void hgemm(
    const __half* __restrict__ A, const __half* __restrict__ B,
    const float* __restrict__ bias, __half* __restrict__ Cout,
    int M, int N, int K) {

    extern __shared__ char sm[];
    const uint32_t base = smem_u32(sm);
    const int tid  = threadIdx.x;
    const int lane = tid & 31;
    const int warp = tid >> 5;
    const int wm = warp >> 2, wn = warp & 3;
    const int bm0 = blockIdx.y * TM;
    const int bn0 = blockIdx.x * TN;

    uint32_t a_rel[2]; const __half* a_src[2];
    #pragma unroll
    for (int i = 0; i < 2; i++) {
        const int id = tid * 2 + i;
        const int r = id >> 2, c = id & 3;
        a_rel[i] = a_off(r, c);
        a_src[i] = A + (size_t)(bm0 + r) * K + c * 8;
    }
    uint32_t b_rel[2]; const __half* b_src[2];
    #pragma unroll
    for (int i = 0; i < 2; i++) {
        const int id = tid * 2 + i;
        const int k = id >> 4, c = id & 15;
        b_rel[i] = b_off(k, c);
        b_src[i] = B + (size_t)k * N + bn0 + c * 8;
    }

    float acc[4][4][4];
    #pragma unroll
    for (int mi = 0; mi < 4; mi++)
        #pragma unroll
        for (int ni = 0; ni < 4; ni++)
            #pragma unroll
            for (int j = 0; j < 4; j++) acc[mi][ni][j] = 0.f;

    const int T = K / TKH;

    auto stage = [&](int s, int kt) {
        const int k0 = kt * TKH;
        const uint32_t sb = base + s * STG;
        #pragma unroll
        for (int i = 0; i < 2; i++) cp16(sb + a_rel[i], a_src[i] + k0);
        #pragma unroll
        for (int i = 0; i < 2; i++) cp16(sb + b_rel[i], b_src[i] + (size_t)k0 * N);
        cp_commit();
    };

    const int l_lo = lane & 15;
    const int l_hi = lane >> 4;

    auto compute = [&](int bufi) {
        const uint32_t buf = base + bufi * STG;
        #pragma unroll
        for (int ks = 0; ks < 2; ks++) {
            uint32_t af[4][4];
            #pragma unroll
            for (int mi = 0; mi < 4; mi++) {
                const int row = wm * 64 + mi * 16 + l_lo;
                ldsm_x4(af[mi], buf + a_off(row, ks * 2 + l_hi));
            }
            uint32_t bf[4][2];
            #pragma unroll
            for (int p = 0; p < 2; p++) {
                const int kl = ks * 16 + l_lo;
                const int nc = wn * 4 + p * 2 + l_hi;
                uint32_t r[4];
                ldsm_x4_t(r, buf + b_off(kl, nc));
                bf[p * 2][0]     = r[0]; bf[p * 2][1]     = r[1];
                bf[p * 2 + 1][0] = r[2]; bf[p * 2 + 1][1] = r[3];
            }
            #pragma unroll
            for (int mi = 0; mi < 4; mi++)
                #pragma unroll
                for (int ni = 0; ni < 4; ni++)
                    mma_f16(acc[mi][ni], af[mi], bf[ni]);
        }
    };

    auto pair_body = [&](int kt, int c0, int c1, int s0, int s1) {
        cp_wait<2>();
        __syncthreads();
        const int n1 = kt + 4;
        if (n1 < T) stage(s0, n1); else cp_commit();
        compute(c0);
        const int n2 = kt + 5;
        if (n2 < T) stage(s1, n2); else cp_commit();
        compute(c1);
    };

    #pragma unroll
    for (int s = 0; s < 4; s++) stage(s, s);

    int kt = 0;
    for (; kt + 6 <= T; kt += 6) {
        pair_body(kt,     0, 1, 4, 5);
        pair_body(kt + 2, 2, 3, 0, 1);
        pair_body(kt + 4, 4, 5, 2, 3);
    }
    for (; kt < T; kt += 2)
        pair_body(kt, kt % 6, (kt + 1) % 6, (kt + 4) % 6, (kt + 5) % 6);

    // ---- epilogue: stage C into smem, then coalesced flush ----
    __syncthreads();   // all warps done reading pipeline buffers
    #pragma unroll
    for (int mi = 0; mi < 4; mi++) {
        const int r0 = wm * 64 + mi * 16 + (lane >> 2);
        #pragma unroll
        for (int ni = 0; ni < 4; ni++) {
            const int cb = wn * 32 + ni * 8 + (lane & 3) * 2;
            const float bb0 = bias[bn0 + cb], bb1 = bias[bn0 + cb + 1];
            float v0 = acc[mi][ni][0] + bb0;
            float v1 = acc[mi][ni][1] + bb1;
            float v2 = acc[mi][ni][2] + bb0;
            float v3 = acc[mi][ni][3] + bb1;
            if (RELU) {
                v0 = fmaxf(v0, 0.f); v1 = fmaxf(v1, 0.f);
                v2 = fmaxf(v2, 0.f); v3 = fmaxf(v3, 0.f);
            }
            __half2 p0 = __floats2half2_rn(v0, v1);
            __half2 p1 = __floats2half2_rn(v2, v3);
            sts32(base + r0 * C_ROWB + cb * 2,       *reinterpret_cast<uint32_t*>(&p0));
            sts32(base + (r0 + 8) * C_ROWB + cb * 2, *reinterpret_cast<uint32_t*>(&p1));
        }
    }
    __syncthreads();
    #pragma unroll
    for (int it = 0; it < 8; it++) {
        const int idx = it * 256 + tid;
        const int row = idx >> 4;       // 16 x 16B chunks per 256B row
        const int ch  = idx & 15;
        uint32_t r[4];
        lds128(base + row * C_ROWB + ch * 16, r);
        uint4 v = make_uint4(r[0], r[1], r[2], r[3]);
        *reinterpret_cast<uint4*>(&Cout[(size_t)(bm0 + row) * N + bn0 + ch * 8]) = v;
    }
}

// -------- prep: convert W1+W2 to half, AND compute sum(ru) (last block) -------
#define NCONV (HD * MD / 4)
#define NCONV_BLKS ((2 * NCONV) / 256)

__global__ void k_prep(const float* __restrict__ W1, const float* __restrict__ W2,
                       __half* __restrict__ W1h, __half* __restrict__ W2h,
                       const float* __restrict__ ru) {
    if (blockIdx.x < NCONV_BLKS) {
        const int i = blockIdx.x * 256 + threadIdx.x;
        const float* in; __half* out; int j;
        if (i < NCONV) { in = W1; out = W1h; j = i; }
        else           { in = W2; out = W2h; j = i - NCONV; }
        float4 f = ((const float4*)in)[j];
        ((__half2*)out)[j * 2]     = __floats2half2_rn(f.x, f.y);
        ((__half2*)out)[j * 2 + 1] = __floats2half2_rn(f.z, f.w);
        return;
    }
    __shared__ float sh[256];
    float s = 0.f;
    for (int i = threadIdx.x; i < NTOK; i += 256) s += ru[i];
    sh[threadIdx.x] = s;
    __syncthreads();
    for (int o = 128; o > 0; o >>= 1) {
        if (threadIdx.x < o) sh[threadIdx.x] += sh[threadIdx.x + o];
        __syncthreads();
    }
    if (threadIdx.x == 0) g_ru_sum = sh[0];
}

// ---------------- K: per-batch gate (w, ru_out) --------------------------------
__global__ void k_gate(const float* __restrict__ att, const float* __restrict__ ru,
                       float* __restrict__ ru_out, float* __restrict__ w_out) {
    const int b = blockIdx.x;
    __shared__ float rg_s[SRCN], rn_s[SRCN], sa_s[SRCN];
    __shared__ float S_sh, T_sh;

    if (threadIdx.x < SRCN) {
        const int s = threadIdx.x;
        const float* arow = att + ((size_t)b * SRCN + s) * SRCN;
        float rg = 0.f;
        #pragma unroll
        for (int j = 0; j < SRCN; j++) rg += arow[j];
        const float base = ru[b * SRCN + s] * GAMMA_F + rg;
        const float rn = (g_ru_sum == 0.0f) ? base : base / (1.0f + GAMMA_F);
        rg_s[s] = rg;
        rn_s[s] = rn;
        sa_s[s] = sqrtf(rn);
    }
    __syncthreads();
    if (threadIdx.x == 0) {
        float S = 0.f, T = 0.f;
        #pragma unroll
        for (int j = 0; j < SRCN; j++) { S += sa_s[j]; T += rn_s[j] * sa_s[j]; }
        S_sh = S; T_sh = T;
    }
    __syncthreads();
    if (threadIdx.x < SRCN) {
        const int s = threadIdx.x;
        const float rn = rn_s[s], rg = rg_s[s];
        const float rm = (rn * S_sh - T_sh > 0.0f) ? 1.0f : 0.0f;
        ru_out[b * SRCN + s] = ALPHA_F * rn * rm + INV_ALPHA_F * rn * (1.0f - rm);
        w_out [b * SRCN + s] = ALPHA_F * rg * rm + INV_ALPHA_F * rg * (1.0f - rm);
    }
}

// ---------------- K: mmh = half(w * LN(v+q)) — pure streaming -------------------
__global__ void k_ln1(const float* __restrict__ v, const float* __restrict__ q,
                      const float* __restrict__ g1, const float* __restrict__ b1,
                      const float* __restrict__ w, __half* __restrict__ mmh) {
    const int t = blockIdx.x;
    const int c0 = threadIdx.x * 4;
    const float4 va = *(const float4*)&v[(size_t)t * HD + c0];
    const float4 qa = *(const float4*)&q[(size_t)t * HD + c0];
    float x[4] = {va.x + qa.x, va.y + qa.y, va.z + qa.z, va.w + qa.w};
    float sm1 = x[0] + x[1] + x[2] + x[3];
    float sm2 = x[0]*x[0] + x[1]*x[1] + x[2]*x[2] + x[3]*x[3];

    __shared__ float sh1[8], sh2[8];
    const int lane = threadIdx.x & 31, wid = threadIdx.x >> 5;
    #pragma unroll
    for (int o = 16; o > 0; o >>= 1) {
        sm1 += __shfl_xor_sync(0xffffffffu, sm1, o);
        sm2 += __shfl_xor_sync(0xffffffffu, sm2, o);
    }
    if (lane == 0) { sh1[wid] = sm1; sh2[wid] = sm2; }
    __syncthreads();
    sm1 = 0.f; sm2 = 0.f;
    #pragma unroll
    for (int i = 0; i < 8; i++) { sm1 += sh1[i]; sm2 += sh2[i]; }

    const float mu   = sm1 * (1.0f / HD);
    const float var  = sm2 * (1.0f / HD) - mu * mu;
    const float rstd = rsqrtf(var + 1e-6f);
    const float ww   = __ldg(&w[t]);

    const float4 ga = *(const float4*)&g1[c0];
    const float4 ba = *(const float4*)&b1[c0];
    float y0 = ww * (ga.x * (x[0] - mu) * rstd + ba.x);
    float y1 = ww * (ga.y * (x[1] - mu) * rstd + ba.y);
    float y2 = ww * (ga.z * (x[2] - mu) * rstd + ba.z);
    float y3 = ww * (ga.w * (x[3] - mu) * rstd + ba.w);
    __half2 p0 = __floats2half2_rn(y0, y1);
    __half2 p1 = __floats2half2_rn(y2, y3);
    uint2 packed;
    packed.x = *reinterpret_cast<uint32_t*>(&p0);
    packed.y = *reinterpret_cast<uint32_t*>(&p1);
    *reinterpret_cast<uint2*>(&mmh[(size_t)t * HD + c0]) = packed;
}

// ---------------- K: out = LN(mmh + fch) ---------------------------------------
__global__ void k_ln2(const __half* __restrict__ mmh, const __half* __restrict__ fch,
                      const float* __restrict__ g2, const float* __restrict__ b2,
                      float* __restrict__ out) {
    const int t = blockIdx.x;
    const int c0 = threadIdx.x * 4;

    const uint2 hm = *(const uint2*)&mmh[(size_t)t * HD + c0];
    const uint2 hf = *(const uint2*)&fch[(size_t)t * HD + c0];
    const float2 m0 = __half22float2(*reinterpret_cast<const __half2*>(&hm.x));
    const float2 m1 = __half22float2(*reinterpret_cast<const __half2*>(&hm.y));
    const float2 f0 = __half22float2(*reinterpret_cast<const __half2*>(&hf.x));
    const float2 f1 = __half22float2(*reinterpret_cast<const __half2*>(&hf.y));

    float x[4] = {m0.x + f0.x, m0.y + f0.y, m1.x + f1.x, m1.y + f1.y};
    float s  = x[0] + x[1] + x[2] + x[3];
    float s2 = x[0]*x[0] + x[1]*x[1] + x[2]*x[2] + x[3]*x[3];

    __shared__ float sh1[8], sh2[8];
    const int lane = threadIdx.x & 31, wid = threadIdx.x >> 5;
    #pragma unroll
    for (int o = 16; o > 0; o >>= 1) {
        s  += __shfl_xor_sync(0xffffffffu, s,  o);
        s2 += __shfl_xor_sync(0xffffffffu, s2, o);
    }
    if (lane == 0) { sh1[wid] = s; sh2[wid] = s2; }
    __syncthreads();
    s = 0.f; s2 = 0.f;
    #pragma unroll
    for (int i = 0; i < 8; i++) { s += sh1[i]; s2 += sh2[i]; }

    const float mu   = s * (1.0f / HD);
    const float var  = s2 * (1.0f / HD) - mu * mu;
    const float rstd = rsqrtf(var + 1e-6f);

    const float4 ga = *(const float4*)&g2[c0];
    const float4 ba = *(const float4*)&b2[c0];
    float4 o4;
    o4.x = ga.x * (x[0] - mu) * rstd + ba.x;
    o4.y = ga.y * (x[1] - mu) * rstd + ba.y;
    o4.z = ga.z * (x[2] - mu) * rstd + ba.z;
    o4.w = ga.w * (x[3] - mu) * rstd + ba.w;
    *(float4*)&out[(size_t)t * HD + c0] = o4;
}

// ---------------- launch --------------------------------------------------------
extern "C" void kernel_launch(void* const* d_in, const int* in_sizes, int n_in,
                              void* d_out, int out_size) {
    const float* v   = (const float*)d_in[0];
    const float* q   = (const float*)d_in[1];
    const float* att = (const float*)d_in[2];
    const float* ru  = (const float*)d_in[3];
    const float* g1  = (const float*)d_in[4];
    const float* b1  = (const float*)d_in[5];
    const float* g2  = (const float*)d_in[6];
    const float* b2  = (const float*)d_in[7];
    const float* W1  = (const float*)d_in[8];
    const float* c1  = (const float*)d_in[9];
    const float* W2  = (const float*)d_in[10];
    const float* c2  = (const float*)d_in[11];

    float* out    = (float*)d_out;
    float* ru_out = out + (size_t)NTOK * HD;

    void *pmmh, *ph, *pfch, *pw1h, *pw2h, *pw;
    cudaGetSymbolAddress(&pmmh, g_mmh);
    cudaGetSymbolAddress(&ph,   g_h);
    cudaGetSymbolAddress(&pfch, g_fch);
    cudaGetSymbolAddress(&pw1h, g_W1h);
    cudaGetSymbolAddress(&pw2h, g_W2h);
    cudaGetSymbolAddress(&pw,   g_w);

    cudaFuncSetAttribute(hgemm<1>, cudaFuncAttributeMaxDynamicSharedMemorySize, SMEM_DYN);
    cudaFuncSetAttribute(hgemm<0>, cudaFuncAttributeMaxDynamicSharedMemorySize, SMEM_DYN);

    // launch #1: weight converts + ru sum (fused)
    k_prep<<<NCONV_BLKS + 1, 256>>>(W1, W2, (__half*)pw1h, (__half*)pw2h, ru);
    // launch #2: per-batch gate
    k_gate<<<BSZ, 64>>>(att, ru, ru_out, (float*)pw);
    // launch #3: pure streaming LN1
    k_ln1<<<NTOK, 256>>>(v, q, g1, b1, (const float*)pw, (__half*)pmmh);
    // launch #4: GEMM1 (profiled)
    hgemm<1><<<dim3(MD / TN, NTOK / TM), 256, SMEM_DYN>>>(
        (const __half*)pmmh, (const __half*)pw1h, c1, (__half*)ph, NTOK, MD, HD);
    // launch #5: GEMM2
    hgemm<0><<<dim3(HD / TN, NTOK / TM), 256, SMEM_DYN>>>(
        (const __half*)ph, (const __half*)pw2h, c2, (__half*)pfch, NTOK, HD, MD);
    // launch #6: LN2
    k_ln2<<<NTOK, 256>>>((const __half*)pmmh, (const __half*)pfch, g2, b2, out);
}

// round 16
// speedup vs baseline: 1.2771x; 1.2771x over previous
#include <cuda_runtime.h>
#include <cuda_fp16.h>
#include <cstdint>

#define BSZ  512
#define SRCN 36
#define HD   1024
#define MD   4096
#define NTOK (BSZ*SRCN)       // 18432
#define ALPHA_F 8.0f
#define INV_ALPHA_F 0.125f
#define GAMMA_F 0.98f

// ---------------- scratch (device globals: allocation-guard safe) ----------
__device__ float g_ru_sum;
__device__ float g_w[NTOK];
__device__ __align__(16) __half g_mmh[(size_t)NTOK * HD];
__device__ __align__(16) __half g_h  [(size_t)NTOK * MD];
__device__ __align__(16) __half g_fch[(size_t)NTOK * HD];
__device__ __align__(16) __half g_W1h[(size_t)HD * MD];
__device__ __align__(16) __half g_W2h[(size_t)MD * HD];

// ---------------- PTX helpers ------------------------------------------------
__device__ __forceinline__ uint32_t smem_u32(const void* p) {
    uint32_t a;
    asm("{ .reg .u64 t; cvta.to.shared.u64 t, %1; cvt.u32.u64 %0, t; }" : "=r"(a) : "l"(p));
    return a;
}
__device__ __forceinline__ void cp16(uint32_t dst, const void* src) {
    asm volatile("cp.async.cg.shared.global [%0], [%1], 16;" :: "r"(dst), "l"(src));
}
__device__ __forceinline__ void cp_commit() {
    asm volatile("cp.async.commit_group;" ::: "memory");
}
template <int N>
__device__ __forceinline__ void cp_wait() {
    asm volatile("cp.async.wait_group %0;" :: "n"(N) : "memory");
}
__device__ __forceinline__ void ldsm_x4(uint32_t* r, uint32_t addr) {
    asm volatile("ldmatrix.sync.aligned.m8n8.x4.shared.b16 {%0,%1,%2,%3}, [%4];"
                 : "=r"(r[0]), "=r"(r[1]), "=r"(r[2]), "=r"(r[3]) : "r"(addr));
}
__device__ __forceinline__ void ldsm_x4_t(uint32_t* r, uint32_t addr) {
    asm volatile("ldmatrix.sync.aligned.m8n8.x4.trans.shared.b16 {%0,%1,%2,%3}, [%4];"
                 : "=r"(r[0]), "=r"(r[1]), "=r"(r[2]), "=r"(r[3]) : "r"(addr));
}
__device__ __forceinline__ void mma_f16(float* c, const uint32_t* a, const uint32_t* b) {
    asm volatile(
        "mma.sync.aligned.m16n8k16.row.col.f32.f16.f16.f32 "
        "{%0,%1,%2,%3},{%4,%5,%6,%7},{%8,%9},{%0,%1,%2,%3};"
        : "+f"(c[0]), "+f"(c[1]), "+f"(c[2]), "+f"(c[3])
        : "r"(a[0]), "r"(a[1]), "r"(a[2]), "r"(a[3]), "r"(b[0]), "r"(b[1]));
}

// ============================ fp16 HMMA GEMM =================================
// R12 champion pipeline: 128x128 block, 2x4 warps of 64x32, TKH=32, 6 stages,
// 2 k-tiles per barrier, race-free re-indexed prefetch, pair loop unrolled 3x.
#define TM 128
#define TN 128
#define TKH 32
#define NSTAGE 6
#define A_STG 8192
#define B_STG 8192
#define STG (A_STG + B_STG)
#define SMEM_DYN (NSTAGE * STG)

__device__ __forceinline__ uint32_t a_off(int row, int c16) {
    const int sr = row >> 1;
    const int ch = (row & 1) * 4 + c16;
    return (uint32_t)(sr * 128 + ((ch ^ (sr & 7)) << 4));
}
__device__ __forceinline__ uint32_t b_off(int k, int c16) {
    return (uint32_t)(A_STG + k * 256 + (((c16 & 8) | ((c16 ^ k) & 7)) << 4));
}

template <int OUT_HALF, int RELU>
__global__ __launch_bounds__(256, 2) void hgemm(
    const __half* __restrict__ A, const __half* __restrict__ B,
    const float* __restrict__ bias, void* __restrict__ Cout,
    int M, int N, int K) {

    extern __shared__ char sm[];
    const uint32_t base = smem_u32(sm);
    const int tid  = threadIdx.x;
    const int lane = tid & 31;
    const int warp = tid >> 5;
    const int wm = warp >> 2, wn = warp & 3;
    const int bm0 = blockIdx.y * TM;
    const int bn0 = blockIdx.x * TN;

    uint32_t a_rel[2]; const __half* a_src[2];
    #pragma unroll
    for (int i = 0; i < 2; i++) {
        const int id = tid * 2 + i;
        const int r = id >> 2, c = id & 3;
        a_rel[i] = a_off(r, c);
        a_src[i] = A + (size_t)(bm0 + r) * K + c * 8;
    }
    uint32_t b_rel[2]; const __half* b_src[2];
    #pragma unroll
    for (int i = 0; i < 2; i++) {
        const int id = tid * 2 + i;
        const int k = id >> 4, c = id & 15;
        b_rel[i] = b_off(k, c);
        b_src[i] = B + (size_t)k * N + bn0 + c * 8;
    }

    float acc[4][4][4];
    #pragma unroll
    for (int mi = 0; mi < 4; mi++)
        #pragma unroll
        for (int ni = 0; ni < 4; ni++)
            #pragma unroll
            for (int j = 0; j < 4; j++) acc[mi][ni][j] = 0.f;

    const int T = K / TKH;

    auto stage = [&](int s, int kt) {
        const int k0 = kt * TKH;
        const uint32_t sb = base + s * STG;
        #pragma unroll
        for (int i = 0; i < 2; i++) cp16(sb + a_rel[i], a_src[i] + k0);
        #pragma unroll
        for (int i = 0; i < 2; i++) cp16(sb + b_rel[i], b_src[i] + (size_t)k0 * N);
        cp_commit();
    };

    const int l_lo = lane & 15;
    const int l_hi = lane >> 4;

    auto compute = [&](int bufi) {
        const uint32_t buf = base + bufi * STG;
        #pragma unroll
        for (int ks = 0; ks < 2; ks++) {
            uint32_t af[4][4];
            #pragma unroll
            for (int mi = 0; mi < 4; mi++) {
                const int row = wm * 64 + mi * 16 + l_lo;
                ldsm_x4(af[mi], buf + a_off(row, ks * 2 + l_hi));
            }
            uint32_t bf[4][2];
            #pragma unroll
            for (int p = 0; p < 2; p++) {
                const int kl = ks * 16 + l_lo;
                const int nc = wn * 4 + p * 2 + l_hi;
                uint32_t r[4];
                ldsm_x4_t(r, buf + b_off(kl, nc));
                bf[p * 2][0]     = r[0]; bf[p * 2][1]     = r[1];
                bf[p * 2 + 1][0] = r[2]; bf[p * 2 + 1][1] = r[3];
            }
            #pragma unroll
            for (int mi = 0; mi < 4; mi++)
                #pragma unroll
                for (int ni = 0; ni < 4; ni++)
                    mma_f16(acc[mi][ni], af[mi], bf[ni]);
        }
    };

    auto pair_body = [&](int kt, int c0, int c1, int s0, int s1) {
        cp_wait<2>();
        __syncthreads();
        const int n1 = kt + 4;
        if (n1 < T) stage(s0, n1); else cp_commit();
        compute(c0);
        const int n2 = kt + 5;
        if (n2 < T) stage(s1, n2); else cp_commit();
        compute(c1);
    };

    #pragma unroll
    for (int s = 0; s < 4; s++) stage(s, s);

    int kt = 0;
    for (; kt + 6 <= T; kt += 6) {
        pair_body(kt,     0, 1, 4, 5);
        pair_body(kt + 2, 2, 3, 0, 1);
        pair_body(kt + 4, 4, 5, 2, 3);
    }
    for (; kt < T; kt += 2)
        pair_body(kt, kt % 6, (kt + 1) % 6, (kt + 4) % 6, (kt + 5) % 6);

    // ---- epilogue ----
    #pragma unroll
    for (int mi = 0; mi < 4; mi++) {
        const int r0 = bm0 + wm * 64 + mi * 16 + (lane >> 2);
        #pragma unroll
        for (int ni = 0; ni < 4; ni++) {
            const int cb = bn0 + wn * 32 + ni * 8 + (lane & 3) * 2;
            const float bb0 = bias[cb], bb1 = bias[cb + 1];
            float v0 = acc[mi][ni][0] + bb0;
            float v1 = acc[mi][ni][1] + bb1;
            float v2 = acc[mi][ni][2] + bb0;
            float v3 = acc[mi][ni][3] + bb1;
            if (RELU) {
                v0 = fmaxf(v0, 0.f); v1 = fmaxf(v1, 0.f);
                v2 = fmaxf(v2, 0.f); v3 = fmaxf(v3, 0.f);
            }
            if (OUT_HALF) {
                __half* Ch = (__half*)Cout;
                *(__half2*)&Ch[(size_t)r0 * N + cb]       = __floats2half2_rn(v0, v1);
                *(__half2*)&Ch[(size_t)(r0 + 8) * N + cb] = __floats2half2_rn(v2, v3);
            } else {
                float* Cf = (float*)Cout;
                *(float2*)&Cf[(size_t)r0 * N + cb]       = make_float2(v0, v1);
                *(float2*)&Cf[(size_t)(r0 + 8) * N + cb] = make_float2(v2, v3);
            }
        }
    }
}

// -------- prep: convert W1+W2 to half, AND compute sum(ru) (last block) -------
#define NCONV (HD * MD / 4)
#define NCONV_BLKS ((2 * NCONV) / 256)

__global__ void k_prep(const float* __restrict__ W1, const float* __restrict__ W2,
                       __half* __restrict__ W1h, __half* __restrict__ W2h,
                       const float* __restrict__ ru) {
    if (blockIdx.x < NCONV_BLKS) {
        const int i = blockIdx.x * 256 + threadIdx.x;
        const float* in; __half* out; int j;
        if (i < NCONV) { in = W1; out = W1h; j = i; }
        else           { in = W2; out = W2h; j = i - NCONV; }
        float4 f = ((const float4*)in)[j];
        ((__half2*)out)[j * 2]     = __floats2half2_rn(f.x, f.y);
        ((__half2*)out)[j * 2 + 1] = __floats2half2_rn(f.z, f.w);
        return;
    }
    __shared__ float sh[256];
    float s = 0.f;
    for (int i = threadIdx.x; i < NTOK; i += 256) s += ru[i];
    sh[threadIdx.x] = s;
    __syncthreads();
    for (int o = 128; o > 0; o >>= 1) {
        if (threadIdx.x < o) sh[threadIdx.x] += sh[threadIdx.x + o];
        __syncthreads();
    }
    if (threadIdx.x == 0) g_ru_sum = sh[0];
}

// ---------------- K: per-batch gate (w, ru_out) --------------------------------
__global__ void k_gate(const float* __restrict__ att, const float* __restrict__ ru,
                       float* __restrict__ ru_out, float* __restrict__ w_out) {
    const int b = blockIdx.x;
    __shared__ float rg_s[SRCN], rn_s[SRCN], sa_s[SRCN];
    __shared__ float S_sh, T_sh;

    if (threadIdx.x < SRCN) {
        const int s = threadIdx.x;
        const float* arow = att + ((size_t)b * SRCN + s) * SRCN;
        float rg = 0.f;
        #pragma unroll
        for (int j = 0; j < SRCN; j++) rg += arow[j];
        const float base = ru[b * SRCN + s] * GAMMA_F + rg;
        const float rn = (g_ru_sum == 0.0f) ? base : base / (1.0f + GAMMA_F);
        rg_s[s] = rg;
        rn_s[s] = rn;
        sa_s[s] = sqrtf(rn);
    }
    __syncthreads();
    if (threadIdx.x == 0) {
        float S = 0.f, T = 0.f;
        #pragma unroll
        for (int j = 0; j < SRCN; j++) { S += sa_s[j]; T += rn_s[j] * sa_s[j]; }
        S_sh = S; T_sh = T;
    }
    __syncthreads();
    if (threadIdx.x < SRCN) {
        const int s = threadIdx.x;
        const float rn = rn_s[s], rg = rg_s[s];
        const float rm = (rn * S_sh - T_sh > 0.0f) ? 1.0f : 0.0f;
        ru_out[b * SRCN + s] = ALPHA_F * rn * rm + INV_ALPHA_F * rn * (1.0f - rm);
        w_out [b * SRCN + s] = ALPHA_F * rg * rm + INV_ALPHA_F * rg * (1.0f - rm);
    }
}

// ---------------- K: mmh = half(w * LN(v+q)) — pure streaming -------------------
__global__ void k_ln1(const float* __restrict__ v, const float* __restrict__ q,
                      const float* __restrict__ g1, const float* __restrict__ b1,
                      const float* __restrict__ w, __half* __restrict__ mmh) {
    const int t = blockIdx.x;
    const int c0 = threadIdx.x * 4;
    const float4 va = *(const float4*)&v[(size_t)t * HD + c0];
    const float4 qa = *(const float4*)&q[(size_t)t * HD + c0];
    float x[4] = {va.x + qa.x, va.y + qa.y, va.z + qa.z, va.w + qa.w};
    float sm1 = x[0] + x[1] + x[2] + x[3];
    float sm2 = x[0]*x[0] + x[1]*x[1] + x[2]*x[2] + x[3]*x[3];

    __shared__ float sh1[8], sh2[8];
    const int lane = threadIdx.x & 31, wid = threadIdx.x >> 5;
    #pragma unroll
    for (int o = 16; o > 0; o >>= 1) {
        sm1 += __shfl_xor_sync(0xffffffffu, sm1, o);
        sm2 += __shfl_xor_sync(0xffffffffu, sm2, o);
    }
    if (lane == 0) { sh1[wid] = sm1; sh2[wid] = sm2; }
    __syncthreads();
    sm1 = 0.f; sm2 = 0.f;
    #pragma unroll
    for (int i = 0; i < 8; i++) { sm1 += sh1[i]; sm2 += sh2[i]; }

    const float mu   = sm1 * (1.0f / HD);
    const float var  = sm2 * (1.0f / HD) - mu * mu;
    const float rstd = rsqrtf(var + 1e-6f);
    const float ww   = __ldg(&w[t]);

    const float4 ga = *(const float4*)&g1[c0];
    const float4 ba = *(const float4*)&b1[c0];
    float y0 = ww * (ga.x * (x[0] - mu) * rstd + ba.x);
    float y1 = ww * (ga.y * (x[1] - mu) * rstd + ba.y);
    float y2 = ww * (ga.z * (x[2] - mu) * rstd + ba.z);
    float y3 = ww * (ga.w * (x[3] - mu) * rstd + ba.w);
    __half2 p0 = __floats2half2_rn(y0, y1);
    __half2 p1 = __floats2half2_rn(y2, y3);
    uint2 packed;
    packed.x = *reinterpret_cast<uint32_t*>(&p0);
    packed.y = *reinterpret_cast<uint32_t*>(&p1);
    *reinterpret_cast<uint2*>(&mmh[(size_t)t * HD + c0]) = packed;
}

// ---------------- K: out = LN(mmh + fch) ---------------------------------------
__global__ void k_ln2(const __half* __restrict__ mmh, const __half* __restrict__ fch,
                      const float* __restrict__ g2, const float* __restrict__ b2,
                      float* __restrict__ out) {
    const int t = blockIdx.x;
    const int c0 = threadIdx.x * 4;

    const uint2 hm = *(const uint2*)&mmh[(size_t)t * HD + c0];
    const uint2 hf = *(const uint2*)&fch[(size_t)t * HD + c0];
    const float2 m0 = __half22float2(*reinterpret_cast<const __half2*>(&hm.x));
    const float2 m1 = __half22float2(*reinterpret_cast<const __half2*>(&hm.y));
    const float2 f0 = __half22float2(*reinterpret_cast<const __half2*>(&hf.x));
    const float2 f1 = __half22float2(*reinterpret_cast<const __half2*>(&hf.y));

    float x[4] = {m0.x + f0.x, m0.y + f0.y, m1.x + f1.x, m1.y + f1.y};
    float s  = x[0] + x[1] + x[2] + x[3];
    float s2 = x[0]*x[0] + x[1]*x[1] + x[2]*x[2] + x[3]*x[3];

    __shared__ float sh1[8], sh2[8];
    const int lane = threadIdx.x & 31, wid = threadIdx.x >> 5;
    #pragma unroll
    for (int o = 16; o > 0; o >>= 1) {
        s  += __shfl_xor_sync(0xffffffffu, s,  o);
        s2 += __shfl_xor_sync(0xffffffffu, s2, o);
    }
    if (lane == 0) { sh1[wid] = s; sh2[wid] = s2; }
    __syncthreads();
    s = 0.f; s2 = 0.f;
    #pragma unroll
    for (int i = 0; i < 8; i++) { s += sh1[i]; s2 += sh2[i]; }

    const float mu   = s * (1.0f / HD);
    const float var  = s2 * (1.0f / HD) - mu * mu;
    const float rstd = rsqrtf(var + 1e-6f);

    const float4 ga = *(const float4*)&g2[c0];
    const float4 ba = *(const float4*)&b2[c0];
    float4 o4;
    o4.x = ga.x * (x[0] - mu) * rstd + ba.x;
    o4.y = ga.y * (x[1] - mu) * rstd + ba.y;
    o4.z = ga.z * (x[2] - mu) * rstd + ba.z;
    o4.w = ga.w * (x[3] - mu) * rstd + ba.w;
    *(float4*)&out[(size_t)t * HD + c0] = o4;
}

// ---------------- launch --------------------------------------------------------
extern "C" void kernel_launch(void* const* d_in, const int* in_sizes, int n_in,
                              void* d_out, int out_size) {
    const float* v   = (const float*)d_in[0];
    const float* q   = (const float*)d_in[1];
    const float* att = (const float*)d_in[2];
    const float* ru  = (const float*)d_in[3];
    const float* g1  = (const float*)d_in[4];
    const float* b1  = (const float*)d_in[5];
    const float* g2  = (const float*)d_in[6];
    const float* b2  = (const float*)d_in[7];
    const float* W1  = (const float*)d_in[8];
    const float* c1  = (const float*)d_in[9];
    const float* W2  = (const float*)d_in[10];
    const float* c2  = (const float*)d_in[11];

    float* out    = (float*)d_out;
    float* ru_out = out + (size_t)NTOK * HD;

    void *pmmh, *ph, *pfch, *pw1h, *pw2h, *pw;
    cudaGetSymbolAddress(&pmmh, g_mmh);
    cudaGetSymbolAddress(&ph,   g_h);
    cudaGetSymbolAddress(&pfch, g_fch);
    cudaGetSymbolAddress(&pw1h, g_W1h);
    cudaGetSymbolAddress(&pw2h, g_W2h);
    cudaGetSymbolAddress(&pw,   g_w);

    cudaFuncSetAttribute(hgemm<1, 1>, cudaFuncAttributeMaxDynamicSharedMemorySize, SMEM_DYN);
    cudaFuncSetAttribute(hgemm<1, 0>, cudaFuncAttributeMaxDynamicSharedMemorySize, SMEM_DYN);

    // launch #1: weight converts + ru sum (fused)
    k_prep<<<NCONV_BLKS + 1, 256>>>(W1, W2, (__half*)pw1h, (__half*)pw2h, ru);
    // launch #2: per-batch gate
    k_gate<<<BSZ, 64>>>(att, ru, ru_out, (float*)pw);
    // launch #3: pure streaming LN1
    k_ln1<<<NTOK, 256>>>(v, q, g1, b1, (const float*)pw, (__half*)pmmh);
    // launch #4: GEMM1 (profiled)
    hgemm<1, 1><<<dim3(MD / TN, NTOK / TM), 256, SMEM_DYN>>>(
        (const __half*)pmmh, (const __half*)pw1h, c1, ph, NTOK, MD, HD);
    // launch #5: GEMM2
    hgemm<1, 0><<<dim3(HD / TN, NTOK / TM), 256, SMEM_DYN>>>(
        (const __half*)ph, (const __half*)pw2h, c2, pfch, NTOK, HD, MD);
    // launch #6: LN2
    k_ln2<<<NTOK, 256>>>((const __half*)pmmh, (const __half*)pfch, g2, b2, out);
}

// round 17
// speedup vs baseline: 1.2820x; 1.0039x over previous
#include <cuda_runtime.h>
#include <cuda_fp16.h>
#include <cstdint>

#define BSZ  512
#define SRCN 36
#define HD   1024
#define MD   4096
#define NTOK (BSZ*SRCN)       // 18432
#define ALPHA_F 8.0f
#define INV_ALPHA_F 0.125f
#define GAMMA_F 0.98f

// ---------------- scratch (device globals: allocation-guard safe) ----------
__device__ float g_ru_sum;
__device__ float g_w[NTOK];
__device__ __align__(16) __half g_mmh[(size_t)NTOK * HD];
__device__ __align__(16) __half g_h  [(size_t)NTOK * MD];
__device__ __align__(16) __half g_fch[(size_t)NTOK * HD];
__device__ __align__(16) __half g_W1h[(size_t)HD * MD];
__device__ __align__(16) __half g_W2h[(size_t)MD * HD];

// ---------------- PTX helpers ------------------------------------------------
__device__ __forceinline__ uint32_t smem_u32(const void* p) {
    uint32_t a;
    asm("{ .reg .u64 t; cvta.to.shared.u64 t, %1; cvt.u32.u64 %0, t; }" : "=r"(a) : "l"(p));
    return a;
}
__device__ __forceinline__ void cp16(uint32_t dst, const void* src) {
    asm volatile("cp.async.cg.shared.global [%0], [%1], 16;" :: "r"(dst), "l"(src));
}
__device__ __forceinline__ void cp_commit() {
    asm volatile("cp.async.commit_group;" ::: "memory");
}
template <int N>
__device__ __forceinline__ void cp_wait() {
    asm volatile("cp.async.wait_group %0;" :: "n"(N) : "memory");
}
__device__ __forceinline__ void ldsm_x4(uint32_t* r, uint32_t addr) {
    asm volatile("ldmatrix.sync.aligned.m8n8.x4.shared.b16 {%0,%1,%2,%3}, [%4];"
                 : "=r"(r[0]), "=r"(r[1]), "=r"(r[2]), "=r"(r[3]) : "r"(addr));
}
__device__ __forceinline__ void ldsm_x4_t(uint32_t* r, uint32_t addr) {
    asm volatile("ldmatrix.sync.aligned.m8n8.x4.trans.shared.b16 {%0,%1,%2,%3}, [%4];"
                 : "=r"(r[0]), "=r"(r[1]), "=r"(r[2]), "=r"(r[3]) : "r"(addr));
}
__device__ __forceinline__ void mma_f16(float* c, const uint32_t* a, const uint32_t* b) {
    asm volatile(
        "mma.sync.aligned.m16n8k16.row.col.f32.f16.f16.f32 "
        "{%0,%1,%2,%3},{%4,%5,%6,%7},{%8,%9},{%0,%1,%2,%3};"
        : "+f"(c[0]), "+f"(c[1]), "+f"(c[2]), "+f"(c[3])
        : "r"(a[0]), "r"(a[1]), "r"(a[2]), "r"(a[3]), "r"(b[0]), "r"(b[1]));
}

// ============================ fp16 HMMA GEMM =================================
// R12 champion pipeline: 128x128 block, 2x4 warps of 64x32, TKH=32, 6 stages,
// 2 k-tiles per barrier, race-free re-indexed prefetch, pair loop unrolled 3x.
// R17: optional converter blocks appended at blockIdx.y >= conv_y0 — they
// fp32->fp16 convert Wconv during GEMM1's drain waves (DRAM-bound work hiding
// under crossbar-bound GEMM blocks).
#define TM 128
#define TN 128
#define TKH 32
#define NSTAGE 6
#define A_STG 8192
#define B_STG 8192
#define STG (A_STG + B_STG)
#define SMEM_DYN (NSTAGE * STG)

__device__ __forceinline__ uint32_t a_off(int row, int c16) {
    const int sr = row >> 1;
    const int ch = (row & 1) * 4 + c16;
    return (uint32_t)(sr * 128 + ((ch ^ (sr & 7)) << 4));
}
__device__ __forceinline__ uint32_t b_off(int k, int c16) {
    return (uint32_t)(A_STG + k * 256 + (((c16 & 8) | ((c16 ^ k) & 7)) << 4));
}

template <int OUT_HALF, int RELU>
__global__ __launch_bounds__(256, 2) void hgemm(
    const __half* __restrict__ A, const __half* __restrict__ B,
    const float* __restrict__ bias, void* __restrict__ Cout,
    int M, int N, int K,
    const float* __restrict__ Wconv, __half* __restrict__ Wconvh,
    unsigned conv_y0) {

    // ---- converter blocks (appended rows): fp32 -> fp16, then exit ----
    if (blockIdx.y >= conv_y0) {
        const int j = ((blockIdx.y - conv_y0) * gridDim.x + blockIdx.x) * 256
                      + threadIdx.x;                       // one float4 each
        float4 f = ((const float4*)Wconv)[j];
        ((__half2*)Wconvh)[j * 2]     = __floats2half2_rn(f.x, f.y);
        ((__half2*)Wconvh)[j * 2 + 1] = __floats2half2_rn(f.z, f.w);
        return;
    }

    extern __shared__ char sm[];
    const uint32_t base = smem_u32(sm);
    const int tid  = threadIdx.x;
    const int lane = tid & 31;
    const int warp = tid >> 5;
    const int wm = warp >> 2, wn = warp & 3;
    const int bm0 = blockIdx.y * TM;
    const int bn0 = blockIdx.x * TN;

    uint32_t a_rel[2]; const __half* a_src[2];
    #pragma unroll
    for (int i = 0; i < 2; i++) {
        const int id = tid * 2 + i;
        const int r = id >> 2, c = id & 3;
        a_rel[i] = a_off(r, c);
        a_src[i] = A + (size_t)(bm0 + r) * K + c * 8;
    }
    uint32_t b_rel[2]; const __half* b_src[2];
    #pragma unroll
    for (int i = 0; i < 2; i++) {
        const int id = tid * 2 + i;
        const int k = id >> 4, c = id & 15;
        b_rel[i] = b_off(k, c);
        b_src[i] = B + (size_t)k * N + bn0 + c * 8;
    }

    float acc[4][4][4];
    #pragma unroll
    for (int mi = 0; mi < 4; mi++)
        #pragma unroll
        for (int ni = 0; ni < 4; ni++)
            #pragma unroll
            for (int j = 0; j < 4; j++) acc[mi][ni][j] = 0.f;

    const int T = K / TKH;

    auto stage = [&](int s, int kt) {
        const int k0 = kt * TKH;
        const uint32_t sb = base + s * STG;
        #pragma unroll
        for (int i = 0; i < 2; i++) cp16(sb + a_rel[i], a_src[i] + k0);
        #pragma unroll
        for (int i = 0; i < 2; i++) cp16(sb + b_rel[i], b_src[i] + (size_t)k0 * N);
        cp_commit();
    };

    const int l_lo = lane & 15;
    const int l_hi = lane >> 4;

    auto compute = [&](int bufi) {
        const uint32_t buf = base + bufi * STG;
        #pragma unroll
        for (int ks = 0; ks < 2; ks++) {
            uint32_t af[4][4];
            #pragma unroll
            for (int mi = 0; mi < 4; mi++) {
                const int row = wm * 64 + mi * 16 + l_lo;
                ldsm_x4(af[mi], buf + a_off(row, ks * 2 + l_hi));
            }
            uint32_t bf[4][2];
            #pragma unroll
            for (int p = 0; p < 2; p++) {
                const int kl = ks * 16 + l_lo;
                const int nc = wn * 4 + p * 2 + l_hi;
                uint32_t r[4];
                ldsm_x4_t(r, buf + b_off(kl, nc));
                bf[p * 2][0]     = r[0]; bf[p * 2][1]     = r[1];
                bf[p * 2 + 1][0] = r[2]; bf[p * 2 + 1][1] = r[3];
            }
            #pragma unroll
            for (int mi = 0; mi < 4; mi++)
                #pragma unroll
                for (int ni = 0; ni < 4; ni++)
                    mma_f16(acc[mi][ni], af[mi], bf[ni]);
        }
    };

    auto pair_body = [&](int kt, int c0, int c1, int s0, int s1) {
        cp_wait<2>();
        __syncthreads();
        const int n1 = kt + 4;
        if (n1 < T) stage(s0, n1); else cp_commit();
        compute(c0);
        const int n2 = kt + 5;
        if (n2 < T) stage(s1, n2); else cp_commit();
        compute(c1);
    };

    #pragma unroll
    for (int s = 0; s < 4; s++) stage(s, s);

    int kt = 0;
    for (; kt + 6 <= T; kt += 6) {
        pair_body(kt,     0, 1, 4, 5);
        pair_body(kt + 2, 2, 3, 0, 1);
        pair_body(kt + 4, 4, 5, 2, 3);
    }
    for (; kt < T; kt += 2)
        pair_body(kt, kt % 6, (kt + 1) % 6, (kt + 4) % 6, (kt + 5) % 6);

    // ---- epilogue ----
    #pragma unroll
    for (int mi = 0; mi < 4; mi++) {
        const int r0 = bm0 + wm * 64 + mi * 16 + (lane >> 2);
        #pragma unroll
        for (int ni = 0; ni < 4; ni++) {
            const int cb = bn0 + wn * 32 + ni * 8 + (lane & 3) * 2;
            const float bb0 = bias[cb], bb1 = bias[cb + 1];
            float v0 = acc[mi][ni][0] + bb0;
            float v1 = acc[mi][ni][1] + bb1;
            float v2 = acc[mi][ni][2] + bb0;
            float v3 = acc[mi][ni][3] + bb1;
            if (RELU) {
                v0 = fmaxf(v0, 0.f); v1 = fmaxf(v1, 0.f);
                v2 = fmaxf(v2, 0.f); v3 = fmaxf(v3, 0.f);
            }
            if (OUT_HALF) {
                __half* Ch = (__half*)Cout;
                *(__half2*)&Ch[(size_t)r0 * N + cb]       = __floats2half2_rn(v0, v1);
                *(__half2*)&Ch[(size_t)(r0 + 8) * N + cb] = __floats2half2_rn(v2, v3);
            } else {
                float* Cf = (float*)Cout;
                *(float2*)&Cf[(size_t)r0 * N + cb]       = make_float2(v0, v1);
                *(float2*)&Cf[(size_t)(r0 + 8) * N + cb] = make_float2(v2, v3);
            }
        }
    }
}

// -------- prep: convert W1 to half, AND compute sum(ru) (last block) ----------
#define NCONV (HD * MD / 4)        // 1M float4 quads per weight matrix
#define NCONV_BLKS (NCONV / 256)   // 4096 blocks for W1

__global__ void k_prep(const float* __restrict__ W1, __half* __restrict__ W1h,
                       const float* __restrict__ ru) {
    if (blockIdx.x < NCONV_BLKS) {
        const int j = blockIdx.x * 256 + threadIdx.x;
        float4 f = ((const float4*)W1)[j];
        ((__half2*)W1h)[j * 2]     = __floats2half2_rn(f.x, f.y);
        ((__half2*)W1h)[j * 2 + 1] = __floats2half2_rn(f.z, f.w);
        return;
    }
    __shared__ float sh[256];
    float s = 0.f;
    for (int i = threadIdx.x; i < NTOK; i += 256) s += ru[i];
    sh[threadIdx.x] = s;
    __syncthreads();
    for (int o = 128; o > 0; o >>= 1) {
        if (threadIdx.x < o) sh[threadIdx.x] += sh[threadIdx.x + o];
        __syncthreads();
    }
    if (threadIdx.x == 0) g_ru_sum = sh[0];
}

// ---------------- K: per-batch gate (w, ru_out) --------------------------------
__global__ void k_gate(const float* __restrict__ att, const float* __restrict__ ru,
                       float* __restrict__ ru_out, float* __restrict__ w_out) {
    const int b = blockIdx.x;
    __shared__ float rg_s[SRCN], rn_s[SRCN], sa_s[SRCN];
    __shared__ float S_sh, T_sh;

    if (threadIdx.x < SRCN) {
        const int s = threadIdx.x;
        const float* arow = att + ((size_t)b * SRCN + s) * SRCN;
        float rg = 0.f;
        #pragma unroll
        for (int j = 0; j < SRCN; j++) rg += arow[j];
        const float base = ru[b * SRCN + s] * GAMMA_F + rg;
        const float rn = (g_ru_sum == 0.0f) ? base : base / (1.0f + GAMMA_F);
        rg_s[s] = rg;
        rn_s[s] = rn;
        sa_s[s] = sqrtf(rn);
    }
    __syncthreads();
    if (threadIdx.x == 0) {
        float S = 0.f, T = 0.f;
        #pragma unroll
        for (int j = 0; j < SRCN; j++) { S += sa_s[j]; T += rn_s[j] * sa_s[j]; }
        S_sh = S; T_sh = T;
    }
    __syncthreads();
    if (threadIdx.x < SRCN) {
        const int s = threadIdx.x;
        const float rn = rn_s[s], rg = rg_s[s];
        const float rm = (rn * S_sh - T_sh > 0.0f) ? 1.0f : 0.0f;
        ru_out[b * SRCN + s] = ALPHA_F * rn * rm + INV_ALPHA_F * rn * (1.0f - rm);
        w_out [b * SRCN + s] = ALPHA_F * rg * rm + INV_ALPHA_F * rg * (1.0f - rm);
    }
}

// ---------------- K: mmh = half(w * LN(v+q)) — pure streaming -------------------
__global__ void k_ln1(const float* __restrict__ v, const float* __restrict__ q,
                      const float* __restrict__ g1, const float* __restrict__ b1,
                      const float* __restrict__ w, __half* __restrict__ mmh) {
    const int t = blockIdx.x;
    const int c0 = threadIdx.x * 4;
    const float4 va = *(const float4*)&v[(size_t)t * HD + c0];
    const float4 qa = *(const float4*)&q[(size_t)t * HD + c0];
    float x[4] = {va.x + qa.x, va.y + qa.y, va.z + qa.z, va.w + qa.w};
    float sm1 = x[0] + x[1] + x[2] + x[3];
    float sm2 = x[0]*x[0] + x[1]*x[1] + x[2]*x[2] + x[3]*x[3];

    __shared__ float sh1[8], sh2[8];
    const int lane = threadIdx.x & 31, wid = threadIdx.x >> 5;
    #pragma unroll
    for (int o = 16; o > 0; o >>= 1) {
        sm1 += __shfl_xor_sync(0xffffffffu, sm1, o);
        sm2 += __shfl_xor_sync(0xffffffffu, sm2, o);
    }
    if (lane == 0) { sh1[wid] = sm1; sh2[wid] = sm2; }
    __syncthreads();
    sm1 = 0.f; sm2 = 0.f;
    #pragma unroll
    for (int i = 0; i < 8; i++) { sm1 += sh1[i]; sm2 += sh2[i]; }

    const float mu   = sm1 * (1.0f / HD);
    const float var  = sm2 * (1.0f / HD) - mu * mu;
    const float rstd = rsqrtf(var + 1e-6f);
    const float ww   = __ldg(&w[t]);

    const float4 ga = *(const float4*)&g1[c0];
    const float4 ba = *(const float4*)&b1[c0];
    float y0 = ww * (ga.x * (x[0] - mu) * rstd + ba.x);
    float y1 = ww * (ga.y * (x[1] - mu) * rstd + ba.y);
    float y2 = ww * (ga.z * (x[2] - mu) * rstd + ba.z);
    float y3 = ww * (ga.w * (x[3] - mu) * rstd + ba.w);
    __half2 p0 = __floats2half2_rn(y0, y1);
    __half2 p1 = __floats2half2_rn(y2, y3);
    uint2 packed;
    packed.x = *reinterpret_cast<uint32_t*>(&p0);
    packed.y = *reinterpret_cast<uint32_t*>(&p1);
    *reinterpret_cast<uint2*>(&mmh[(size_t)t * HD + c0]) = packed;
}

// ---------------- K: out = LN(mmh + fch) ---------------------------------------
__global__ void k_ln2(const __half* __restrict__ mmh, const __half* __restrict__ fch,
                      const float* __restrict__ g2, const float* __restrict__ b2,
                      float* __restrict__ out) {
    const int t = blockIdx.x;
    const int c0 = threadIdx.x * 4;

    const uint2 hm = *(const uint2*)&mmh[(size_t)t * HD + c0];
    const uint2 hf = *(const uint2*)&fch[(size_t)t * HD + c0];
    const float2 m0 = __half22float2(*reinterpret_cast<const __half2*>(&hm.x));
    const float2 m1 = __half22float2(*reinterpret_cast<const __half2*>(&hm.y));
    const float2 f0 = __half22float2(*reinterpret_cast<const __half2*>(&hf.x));
    const float2 f1 = __half22float2(*reinterpret_cast<const __half2*>(&hf.y));

    float x[4] = {m0.x + f0.x, m0.y + f0.y, m1.x + f1.x, m1.y + f1.y};
    float s  = x[0] + x[1] + x[2] + x[3];
    float s2 = x[0]*x[0] + x[1]*x[1] + x[2]*x[2] + x[3]*x[3];

    __shared__ float sh1[8], sh2[8];
    const int lane = threadIdx.x & 31, wid = threadIdx.x >> 5;
    #pragma unroll
    for (int o = 16; o > 0; o >>= 1) {
        s  += __shfl_xor_sync(0xffffffffu, s,  o);
        s2 += __shfl_xor_sync(0xffffffffu, s2, o);
    }
    if (lane == 0) { sh1[wid] = s; sh2[wid] = s2; }
    __syncthreads();
    s = 0.f; s2 = 0.f;
    #pragma unroll
    for (int i = 0; i < 8; i++) { s += sh1[i]; s2 += sh2[i]; }

    const float mu   = s * (1.0f / HD);
    const float var  = s2 * (1.0f / HD) - mu * mu;
    const float rstd = rsqrtf(var + 1e-6f);

    const float4 ga = *(const float4*)&g2[c0];
    const float4 ba = *(const float4*)&b2[c0];
    float4 o4;
    o4.x = ga.x * (x[0] - mu) * rstd + ba.x;
    o4.y = ga.y * (x[1] - mu) * rstd + ba.y;
    o4.z = ga.z * (x[2] - mu) * rstd + ba.z;
    o4.w = ga.w * (x[3] - mu) * rstd + ba.w;
    *(float4*)&out[(size_t)t * HD + c0] = o4;
}

// ---------------- launch --------------------------------------------------------
extern "C" void kernel_launch(void* const* d_in, const int* in_sizes, int n_in,
                              void* d_out, int out_size) {
    const float* v   = (const float*)d_in[0];
    const float* q   = (const float*)d_in[1];
    const float* att = (const float*)d_in[2];
    const float* ru  = (const float*)d_in[3];
    const float* g1  = (const float*)d_in[4];
    const float* b1  = (const float*)d_in[5];
    const float* g2  = (const float*)d_in[6];
    const float* b2  = (const float*)d_in[7];
    const float* W1  = (const float*)d_in[8];
    const float* c1  = (const float*)d_in[9];
    const float* W2  = (const float*)d_in[10];
    const float* c2  = (const float*)d_in[11];

    float* out    = (float*)d_out;
    float* ru_out = out + (size_t)NTOK * HD;

    void *pmmh, *ph, *pfch, *pw1h, *pw2h, *pw;
    cudaGetSymbolAddress(&pmmh, g_mmh);
    cudaGetSymbolAddress(&ph,   g_h);
    cudaGetSymbolAddress(&pfch, g_fch);
    cudaGetSymbolAddress(&pw1h, g_W1h);
    cudaGetSymbolAddress(&pw2h, g_W2h);
    cudaGetSymbolAddress(&pw,   g_w);

    cudaFuncSetAttribute(hgemm<1, 1>, cudaFuncAttributeMaxDynamicSharedMemorySize, SMEM_DYN);
    cudaFuncSetAttribute(hgemm<1, 0>, cudaFuncAttributeMaxDynamicSharedMemorySize, SMEM_DYN);

    // launch #1: W1 convert + ru sum (fused)
    k_prep<<<NCONV_BLKS + 1, 256>>>(W1, (__half*)pw1h, ru);
    // launch #2: per-batch gate
    k_gate<<<BSZ, 64>>>(att, ru, ru_out, (float*)pw);
    // launch #3: pure streaming LN1
    k_ln1<<<NTOK, 256>>>(v, q, g1, b1, (const float*)pw, (__half*)pmmh);
    // launch #4: GEMM1 (profiled) + W2 conversion in appended grid rows
    //   GEMM rows: y in [0,144); converter rows: y in [144, 144+128) -> 4096 blocks
    hgemm<1, 1><<<dim3(MD / TN, NTOK / TM + NCONV_BLKS / (MD / TN)), 256, SMEM_DYN>>>(
        (const __half*)pmmh, (const __half*)pw1h, c1, ph, NTOK, MD, HD,
        W2, (__half*)pw2h, NTOK / TM);
    // launch #5: GEMM2 (no converter rows)
    hgemm<1, 0><<<dim3(HD / TN, NTOK / TM), 256, SMEM_DYN>>>(
        (const __half*)ph, (const __half*)pw2h, c2, pfch, NTOK, HD, MD,
        nullptr, nullptr, 0x40000000u);
    // launch #6: LN2
    k_ln2<<<NTOK, 256>>>((const __half*)pmmh, (const __half*)pfch, g2, b2, out);
}